// round 2
// baseline (speedup 1.0000x reference)
#include <cuda_runtime.h>
#include <cuda_bf16.h>
#include <math.h>

// ---------------- problem constants ----------------
#define NN0 100000
#define NN1 20000
#define NN2 4000
#define RR 3
#define EE0 160000
#define EE1 64000
#define HID 128
#define FEAT 256      // F_IN = HID + TSS + RS
#define CDIV(a,b) (((a)+(b)-1)/(b))

// ---------------- device scratch (static; no runtime alloc) ----------------
__device__ float g_feat0[(size_t)NN0 * FEAT];          // [N0,256]
__device__ float g_agg[(size_t)RR * NN1 * 768];        // [R,n_dst,768] (mx|mean|sum)
__device__ float g_scratch[(size_t)RR * NN1 * FEAT];   // inp [R,n,256] / tanh buf [R*n,128]
__device__ float g_z[(size_t)RR * NN1 * HID];          // z per relation
__device__ float g_feat1[(size_t)NN1 * FEAT];          // [N1,256]
__device__ float g_h2[(size_t)NN2 * HID];              // [N2,128]
__device__ float g_wsum[RR];                           // attention score sums
__device__ int   g_cnt[RR * NN1];                      // histogram / cursor
__device__ int   g_rowp[RR * NN1 + 1];                 // CSR row pointers
__device__ int   g_csr[RR * EE0];                      // CSR src ids

// ---------------- small helpers ----------------
__device__ __forceinline__ float4 f4add(float4 a, float4 b){
    return make_float4(a.x+b.x, a.y+b.y, a.z+b.z, a.w+b.w);
}
__device__ __forceinline__ float4 f4max(float4 a, float4 b){
    return make_float4(fmaxf(a.x,b.x), fmaxf(a.y,b.y), fmaxf(a.z,b.z), fmaxf(a.w,b.w));
}
__device__ __forceinline__ float4 f4scale(float4 a, float s){
    return make_float4(a.x*s, a.y*s, a.z*s, a.w*s);
}

// ---------------- generic SGEMM: C[M,128] = act(A[M,K] @ B[K,128] + bias) ----------------
// batched over blockIdx.z with element strides; ACT: 0=none 1=relu 2=tanh
template<int ACT>
__global__ __launch_bounds__(256, 2)
void sgemm128(const float* __restrict__ A, const float* __restrict__ B,
              const float* __restrict__ bias, float* __restrict__ C,
              int M, int K, int ldc, int coff,
              long sA, long sB, long sBias, long sC)
{
    A    += (long)blockIdx.z * sA;
    B    += (long)blockIdx.z * sB;
    bias += (long)blockIdx.z * sBias;
    C    += (long)blockIdx.z * sC;

    const int bm  = blockIdx.x * 128;
    const int tid = threadIdx.x;

    __shared__ float As[8][128];
    __shared__ float Bs[8][128];

    const int aRow = tid >> 1;            // 0..127
    const int aCol = (tid & 1) * 4;       // 0 or 4
    const int bRow = tid >> 5;            // 0..7
    const int bCol = (tid & 31) * 4;      // 0..124

    float acc[8][8];
    #pragma unroll
    for (int i = 0; i < 8; i++)
        #pragma unroll
        for (int j = 0; j < 8; j++) acc[i][j] = 0.f;

    const int ty = tid >> 4;   // 0..15
    const int tx = tid & 15;   // 0..15

    for (int k0 = 0; k0 < K; k0 += 8) {
        float4 av = make_float4(0.f, 0.f, 0.f, 0.f);
        int gr = bm + aRow;
        if (gr < M) av = *(const float4*)(A + (long)gr * K + k0 + aCol);
        As[aCol + 0][aRow] = av.x;
        As[aCol + 1][aRow] = av.y;
        As[aCol + 2][aRow] = av.z;
        As[aCol + 3][aRow] = av.w;

        float4 bv = *(const float4*)(B + (long)(k0 + bRow) * 128 + bCol);
        *(float4*)&Bs[bRow][bCol] = bv;

        __syncthreads();

        #pragma unroll
        for (int kk = 0; kk < 8; kk++) {
            float ra[8], rb[8];
            #pragma unroll
            for (int i = 0; i < 8; i++) ra[i] = As[kk][ty * 8 + i];
            #pragma unroll
            for (int j = 0; j < 8; j++) rb[j] = Bs[kk][tx * 8 + j];
            #pragma unroll
            for (int i = 0; i < 8; i++)
                #pragma unroll
                for (int j = 0; j < 8; j++)
                    acc[i][j] = fmaf(ra[i], rb[j], acc[i][j]);
        }
        __syncthreads();
    }

    float bb[8];
    #pragma unroll
    for (int j = 0; j < 8; j++) bb[j] = bias[tx * 8 + j];

    #pragma unroll
    for (int i = 0; i < 8; i++) {
        int row = bm + ty * 8 + i;
        if (row < M) {
            float* crow = C + (long)row * ldc + coff + tx * 8;
            #pragma unroll
            for (int j = 0; j < 8; j++) {
                float v = acc[i][j] + bb[j];
                if (ACT == 1) v = fmaxf(v, 0.f);
                if (ACT == 2) v = tanhf(v);
                crow[j] = v;
            }
        }
    }
}

// ---------------- gather tss/rs embeds into feature cols [128,256) ----------------
__global__ void gather_embed(const float* __restrict__ tss, const float* __restrict__ rs,
                             const int* __restrict__ nid, float* __restrict__ feat, int n)
{
    int gw   = (blockIdx.x * blockDim.x + threadIdx.x) >> 5;
    int lane = threadIdx.x & 31;
    if (gw >= n) return;
    int id = nid[gw];
    float4* out = (float4*)(feat + (long)gw * FEAT);
    if (lane < 16) {
        out[32 + lane] = ((const float4*)(tss + (long)id * 64))[lane];
    } else {
        out[48 + (lane - 16)] = ((const float4*)(rs + (long)id * 64))[lane - 16];
    }
}

// ---------------- CSR build ----------------
__global__ void zero_cnt(int n)
{
    int i = blockIdx.x * blockDim.x + threadIdx.x;
    if (i < n) g_cnt[i] = 0;
}

__global__ void hist_kernel(const int* __restrict__ dst, int total, int E, int ndst)
{
    int i = blockIdx.x * blockDim.x + threadIdx.x;
    if (i >= total) return;
    int r = i / E;
    atomicAdd(&g_cnt[r * ndst + dst[i]], 1);
}

__global__ void scan_kernel(int n)   // exclusive scan of g_cnt -> g_rowp, then zero g_cnt
{
    __shared__ int ssum[1024];
    int tid   = threadIdx.x;
    int chunk = (n + 1023) >> 10;
    int base  = tid * chunk;
    int end   = min(base + chunk, n);

    int s = 0;
    for (int i = base; i < end; i++) s += g_cnt[i];
    ssum[tid] = s;
    __syncthreads();

    for (int off = 1; off < 1024; off <<= 1) {
        int v = (tid >= off) ? ssum[tid - off] : 0;
        __syncthreads();
        ssum[tid] += v;
        __syncthreads();
    }

    int p = ssum[tid] - s;   // exclusive prefix
    for (int i = base; i < end; i++) { g_rowp[i] = p; p += g_cnt[i]; }
    if (tid == 1023) g_rowp[n] = ssum[1023];
    __syncthreads();
    for (int i = tid; i < n; i += 1024) g_cnt[i] = 0;
}

__global__ void scatter_kernel(const int* __restrict__ src, const int* __restrict__ dst,
                               int total, int E, int ndst)
{
    int i = blockIdx.x * blockDim.x + threadIdx.x;
    if (i >= total) return;
    int r   = i / E;
    int idx = r * ndst + dst[i];
    int pos = g_rowp[idx] + atomicAdd(&g_cnt[idx], 1);
    g_csr[pos] = src[i];
}

// ---------------- warp-per-dst aggregation: writes [mx | mean | sum] row of 768 ----------------
__global__ void aggregate_kernel(const float* __restrict__ feat, float* __restrict__ agg, int total)
{
    int gw   = (blockIdx.x * blockDim.x + threadIdx.x) >> 5;
    int lane = threadIdx.x & 31;
    if (gw >= total) return;

    int s = g_rowp[gw], e = g_rowp[gw + 1];
    float4 sa = make_float4(0.f, 0.f, 0.f, 0.f), sb = sa;
    float4 ma = make_float4(-INFINITY, -INFINITY, -INFINITY, -INFINITY), mb = ma;

    for (int i = s; i < e; i++) {
        int srcn = g_csr[i];
        const float4* p = (const float4*)(feat + (long)srcn * FEAT);
        float4 va = p[lane];
        float4 vb = p[lane + 32];
        sa = f4add(sa, va);  sb = f4add(sb, vb);
        ma = f4max(ma, va);  mb = f4max(mb, vb);
    }

    float deg = (float)(e - s);
    if (e == s) { ma = make_float4(0.f,0.f,0.f,0.f); mb = ma; }
    float inv = 1.f / fmaxf(deg, 1.f);

    float4* o = (float4*)(agg + (long)gw * 768);
    o[lane]       = ma;                 o[32 + lane]  = mb;
    o[64 + lane]  = f4scale(sa, inv);   o[96 + lane]  = f4scale(sb, inv);
    o[128 + lane] = sa;                 o[160 + lane] = sb;
}

// ---------------- attention: score reduce + combine ----------------
__global__ void zero_wsum()
{
    if (threadIdx.x < RR) g_wsum[threadIdx.x] = 0.f;
}

__global__ void attn_reduce(const float* __restrict__ T, const float* __restrict__ w2, int N)
{
    int r = blockIdx.y;
    long total = (long)N * HID;
    const float* Tr = T + (long)r * total;

    float s = 0.f;
    for (long i = (long)blockIdx.x * blockDim.x + threadIdx.x; i < total;
         i += (long)gridDim.x * blockDim.x)
        s += Tr[i] * w2[(int)(i & 127)];

    // block reduce
    for (int off = 16; off > 0; off >>= 1) s += __shfl_down_sync(0xffffffffu, s, off);
    __shared__ float sm[8];
    int wid = threadIdx.x >> 5, lane = threadIdx.x & 31;
    if (lane == 0) sm[wid] = s;
    __syncthreads();
    if (wid == 0) {
        s = (lane < (blockDim.x >> 5)) ? sm[lane] : 0.f;
        for (int off = 4; off > 0; off >>= 1) s += __shfl_down_sync(0xffffffffu, s, off);
        if (lane == 0) atomicAdd(&g_wsum[r], s);
    }
}

__global__ void combine_kernel(const float* __restrict__ z, int N,
                               float* __restrict__ out, int ldo,
                               const float* __restrict__ tss, const float* __restrict__ rs,
                               const int* __restrict__ nid, int do_relu, int do_gather)
{
    int gw   = (blockIdx.x * blockDim.x + threadIdx.x) >> 5;
    int lane = threadIdx.x & 31;
    if (gw >= N) return;

    float w0 = g_wsum[0] / (float)N;
    float w1 = g_wsum[1] / (float)N;
    float w2 = g_wsum[2] / (float)N;
    float m  = fmaxf(w0, fmaxf(w1, w2));
    float e0 = expf(w0 - m), e1 = expf(w1 - m), e2 = expf(w2 - m);
    float inv = 1.f / (e0 + e1 + e2);
    float b0 = e0 * inv, b1 = e1 * inv, b2 = e2 * inv;

    long stride = (long)N * HID;
    const float4* z0 = (const float4*)(z + (long)gw * HID);
    const float4* z1 = (const float4*)(z + stride + (long)gw * HID);
    const float4* z2 = (const float4*)(z + 2 * stride + (long)gw * HID);
    float4 v0 = z0[lane], v1 = z1[lane], v2 = z2[lane];
    float4 h;
    h.x = b0 * v0.x + b1 * v1.x + b2 * v2.x;
    h.y = b0 * v0.y + b1 * v1.y + b2 * v2.y;
    h.z = b0 * v0.z + b1 * v1.z + b2 * v2.z;
    h.w = b0 * v0.w + b1 * v1.w + b2 * v2.w;
    if (do_relu) { h.x = fmaxf(h.x, 0.f); h.y = fmaxf(h.y, 0.f); h.z = fmaxf(h.z, 0.f); h.w = fmaxf(h.w, 0.f); }

    float4* orow = (float4*)(out + (long)gw * ldo);
    orow[lane] = h;

    if (do_gather) {
        int id = nid[gw];
        if (lane < 16) orow[32 + lane] = ((const float4*)(tss + (long)id * 64))[lane];
        else           orow[48 + (lane - 16)] = ((const float4*)(rs + (long)id * 64))[lane - 16];
    }
}

// ---------------- final prediction ----------------
__global__ void pred_kernel(const float* __restrict__ h, const float* __restrict__ pw,
                            const float* __restrict__ pb, float* __restrict__ out, int N)
{
    int gw   = (blockIdx.x * blockDim.x + threadIdx.x) >> 5;
    int lane = threadIdx.x & 31;
    if (gw >= N) return;
    float4 v = ((const float4*)(h + (long)gw * HID))[lane];
    float4 w = ((const float4*)pw)[lane];
    float s  = v.x * w.x + v.y * w.y + v.z * w.z + v.w * w.w;
    for (int off = 16; off > 0; off >>= 1) s += __shfl_down_sync(0xffffffffu, s, off);
    if (lane == 0) out[gw] = 1.f / (1.f + expf(-(s + pb[0])));
}

// ---------------- host ----------------
extern "C" void kernel_launch(void* const* d_in, const int* in_sizes, int n_in,
                              void* d_out, int out_size)
{
    const float* x_user   = (const float*)d_in[0];
    const float* tss      = (const float*)d_in[1];
    const float* rs       = (const float*)d_in[2];
    const int*   src_nid0 = (const int*)  d_in[3];
    const int*   src_nid1 = (const int*)  d_in[4];
    const int*   e0_src   = (const int*)  d_in[5];
    const int*   e0_dst   = (const int*)  d_in[6];
    const int*   e1_src   = (const int*)  d_in[7];
    const int*   e1_dst   = (const int*)  d_in[8];
    const float* embed_w  = (const float*)d_in[9];
    const float* embed_b  = (const float*)d_in[10];
    const float* l1_fc1_w = (const float*)d_in[11];
    const float* l1_fc1_b = (const float*)d_in[12];
    const float* l1_fc2_w = (const float*)d_in[13];
    const float* l1_fc2_b = (const float*)d_in[14];
    const float* l1_fc3_w = (const float*)d_in[15];
    const float* l1_fc3_b = (const float*)d_in[16];
    const float* l2_fc1_w = (const float*)d_in[17];
    const float* l2_fc1_b = (const float*)d_in[18];
    const float* l2_fc2_w = (const float*)d_in[19];
    const float* l2_fc2_b = (const float*)d_in[20];
    const float* l2_fc3_w = (const float*)d_in[21];
    const float* l2_fc3_b = (const float*)d_in[22];
    const float* attn_w1  = (const float*)d_in[23];
    const float* attn_b1  = (const float*)d_in[24];
    const float* attn_w2  = (const float*)d_in[25];
    const float* pred_w   = (const float*)d_in[26];
    const float* pred_b   = (const float*)d_in[27];
    float* out = (float*)d_out;

    float *feat0, *agg, *scratch, *z, *feat1, *h2;
    cudaGetSymbolAddress((void**)&feat0,   g_feat0);
    cudaGetSymbolAddress((void**)&agg,     g_agg);
    cudaGetSymbolAddress((void**)&scratch, g_scratch);
    cudaGetSymbolAddress((void**)&z,       g_z);
    cudaGetSymbolAddress((void**)&feat1,   g_feat1);
    cudaGetSymbolAddress((void**)&h2,      g_h2);

    // ---- embed + feat0 ----
    sgemm128<0><<<dim3(CDIV(NN0,128),1,1),256>>>(x_user, embed_w, embed_b, feat0,
                                                 NN0, 128, FEAT, 0, 0,0,0,0);
    gather_embed<<<CDIV(NN0*32,256),256>>>(tss, rs, src_nid0, feat0, NN0);

    // ---- layer 1 CSR + aggregate ----
    zero_cnt<<<CDIV(RR*NN1,256),256>>>(RR*NN1);
    hist_kernel<<<CDIV(RR*EE0,256),256>>>(e0_dst, RR*EE0, EE0, NN1);
    scan_kernel<<<1,1024>>>(RR*NN1);
    scatter_kernel<<<CDIV(RR*EE0,256),256>>>(e0_src, e0_dst, RR*EE0, EE0, NN1);
    aggregate_kernel<<<CDIV(RR*NN1*32,256),256>>>(feat0, agg, RR*NN1);

    // ---- layer 1 GEMMs (batched over relations) ----
    sgemm128<1><<<dim3(CDIV(NN1,128),1,RR),256>>>(agg,   l1_fc2_w, l1_fc2_b, scratch,
        NN1, 768, FEAT, 0,   (long)NN1*768, 768*128, 128, (long)NN1*FEAT);
    sgemm128<1><<<dim3(CDIV(NN1,128),1,RR),256>>>(feat0, l1_fc1_w, l1_fc1_b, scratch,
        NN1, 256, FEAT, 128, 0,             256*128, 128, (long)NN1*FEAT);
    sgemm128<0><<<dim3(CDIV(NN1,128),1,RR),256>>>(scratch, l1_fc3_w, l1_fc3_b, z,
        NN1, 256, HID, 0,    (long)NN1*FEAT, 256*128, 128, (long)NN1*HID);

    // ---- attention 1 -> feat1 ----
    sgemm128<2><<<dim3(CDIV(RR*NN1,128),1,1),256>>>(z, attn_w1, attn_b1, scratch,
        RR*NN1, 128, 128, 0, 0,0,0,0);
    zero_wsum<<<1,32>>>();
    attn_reduce<<<dim3(240,RR),256>>>(scratch, attn_w2, NN1);
    combine_kernel<<<CDIV(NN1*32,256),256>>>(z, NN1, feat1, FEAT, tss, rs, src_nid1, 1, 1);

    // ---- layer 2 CSR + aggregate ----
    zero_cnt<<<CDIV(RR*NN2,256),256>>>(RR*NN2);
    hist_kernel<<<CDIV(RR*EE1,256),256>>>(e1_dst, RR*EE1, EE1, NN2);
    scan_kernel<<<1,1024>>>(RR*NN2);
    scatter_kernel<<<CDIV(RR*EE1,256),256>>>(e1_src, e1_dst, RR*EE1, EE1, NN2);
    aggregate_kernel<<<CDIV(RR*NN2*32,256),256>>>(feat1, agg, RR*NN2);

    // ---- layer 2 GEMMs ----
    sgemm128<1><<<dim3(CDIV(NN2,128),1,RR),256>>>(agg,   l2_fc2_w, l2_fc2_b, scratch,
        NN2, 768, FEAT, 0,   (long)NN2*768, 768*128, 128, (long)NN2*FEAT);
    sgemm128<1><<<dim3(CDIV(NN2,128),1,RR),256>>>(feat1, l2_fc1_w, l2_fc1_b, scratch,
        NN2, 256, FEAT, 128, 0,             256*128, 128, (long)NN2*FEAT);
    sgemm128<0><<<dim3(CDIV(NN2,128),1,RR),256>>>(scratch, l2_fc3_w, l2_fc3_b, z,
        NN2, 256, HID, 0,    (long)NN2*FEAT, 256*128, 128, (long)NN2*HID);

    // ---- attention 2 -> h2 -> prediction ----
    sgemm128<2><<<dim3(CDIV(RR*NN2,128),1,1),256>>>(z, attn_w1, attn_b1, scratch,
        RR*NN2, 128, 128, 0, 0,0,0,0);
    zero_wsum<<<1,32>>>();
    attn_reduce<<<dim3(48,RR),256>>>(scratch, attn_w2, NN2);
    combine_kernel<<<CDIV(NN2*32,256),256>>>(z, NN2, h2, HID, (const float*)0, (const float*)0,
                                             (const int*)0, 0, 0);
    pred_kernel<<<CDIV(NN2*32,256),256>>>(h2, pred_w, pred_b, out, NN2);
}

// round 3
// speedup vs baseline: 1.6389x; 1.6389x over previous
#include <cuda_runtime.h>
#include <cuda_bf16.h>
#include <math.h>
#include <stdint.h>

// ---------------- problem constants ----------------
#define NN0 100000
#define NN1 20000
#define NN2 4000
#define RR 3
#define EE0 160000
#define EE1 64000
#define HID 128
#define FEAT 256      // F_IN = HID + TSS + RS
#define CDIV(a,b) (((a)+(b)-1)/(b))

// ---------------- device scratch (static; no runtime alloc) ----------------
__device__ float g_feat0[(size_t)NN0 * FEAT];          // [N0,256]
__device__ float g_agg[(size_t)RR * NN1 * 768];        // [R,n_dst,768] (mx|mean|sum)
__device__ float g_scratch[(size_t)RR * NN1 * FEAT];   // inp [R,n,256] / tanh buf [R*n,128]
__device__ float g_z[(size_t)RR * NN1 * HID];          // z per relation
__device__ float g_feat1[(size_t)NN1 * FEAT];          // [N1,256]
__device__ float g_h2[(size_t)NN2 * HID];              // [N2,128]
__device__ float g_wsum[RR];                           // attention score sums
__device__ int   g_cnt[RR * NN1];                      // histogram / cursor
__device__ int   g_rowp[RR * NN1 + 1];                 // CSR row pointers
__device__ int   g_csr[RR * EE0];                      // CSR src ids

// split-bf16 weights, transposed to [n=128][K] layout
#define W_TOTAL 1015808
__device__ __align__(16) __nv_bfloat16 g_whi[W_TOTAL];
__device__ __align__(16) __nv_bfloat16 g_wlo[W_TOTAL];

// offsets (elements) into g_whi/g_wlo
#define OFF_EMBED  0
#define OFF_L1FC1  16384
#define OFF_L1FC2  114688
#define OFF_L1FC3  409600
#define OFF_L2FC1  507904
#define OFF_L2FC2  606208
#define OFF_L2FC3  901120
#define OFF_ATTN   999424

// ---------------- small helpers ----------------
__device__ __forceinline__ float4 f4add(float4 a, float4 b){
    return make_float4(a.x+b.x, a.y+b.y, a.z+b.z, a.w+b.w);
}
__device__ __forceinline__ float4 f4max(float4 a, float4 b){
    return make_float4(fmaxf(a.x,b.x), fmaxf(a.y,b.y), fmaxf(a.z,b.z), fmaxf(a.w,b.w));
}
__device__ __forceinline__ float4 f4scale(float4 a, float s){
    return make_float4(a.x*s, a.y*s, a.z*s, a.w*s);
}

#define MMA_BF16(D, A, B0, B1) \
  asm volatile("mma.sync.aligned.m16n8k16.row.col.f32.bf16.bf16.f32 " \
    "{%0,%1,%2,%3}, {%4,%5,%6,%7}, {%8,%9}, {%0,%1,%2,%3};\n" \
    : "+f"((D)[0]), "+f"((D)[1]), "+f"((D)[2]), "+f"((D)[3]) \
    : "r"((A)[0]), "r"((A)[1]), "r"((A)[2]), "r"((A)[3]), "r"(B0), "r"(B1))

// ---------------- weight transpose+split: W[K][128] -> Whi/Wlo [128][K] ----------------
__global__ void split_w(const float* __restrict__ W, __nv_bfloat16* __restrict__ Whi,
                        __nv_bfloat16* __restrict__ Wlo, int K)
{
    __shared__ float sm[32][33];
    int k0 = blockIdx.x * 32, n0 = blockIdx.y * 32;
    long woff = (long)blockIdx.z * K * 128;
    W += woff; Whi += woff; Wlo += woff;
    int tx = threadIdx.x, ty = threadIdx.y;
    #pragma unroll
    for (int i = 0; i < 4; i++)
        sm[ty + i * 8][tx] = W[(long)(k0 + ty + i * 8) * 128 + n0 + tx];
    __syncthreads();
    #pragma unroll
    for (int i = 0; i < 4; i++) {
        float x = sm[tx][ty + i * 8];
        __nv_bfloat16 h = __float2bfloat16(x);
        float r = x - __bfloat162float(h);
        int n = n0 + ty + i * 8;
        Whi[(long)n * K + k0 + tx] = h;
        Wlo[(long)n * K + k0 + tx] = __float2bfloat16(r);
    }
}

// ---------------- tensor-core GEMM: C[M,128] = act(A[M,K] @ W[K,128] + bias) ----------------
// W given pre-split+transposed as Bhi/Blo [128][K]. batched over blockIdx.z.
// ACT: 0=none 1=relu 2=tanh
template<int ACT>
__global__ __launch_bounds__(256)
void tc_gemm(const float* __restrict__ A, const __nv_bfloat16* __restrict__ Bhi,
             const __nv_bfloat16* __restrict__ Blo, const float* __restrict__ bias,
             float* __restrict__ C, int M, int K, int ldc, int coff,
             long sA, long sW, long sBias, long sC)
{
    A    += (long)blockIdx.z * sA;
    Bhi  += (long)blockIdx.z * sW;
    Blo  += (long)blockIdx.z * sW;
    bias += (long)blockIdx.z * sBias;
    C    += (long)blockIdx.z * sC;

    const int bm   = blockIdx.x * 128;
    const int tid  = threadIdx.x;
    const int lane = tid & 31;
    const int w    = tid >> 5;
    const int wm   = w & 3;          // 4 m-warps
    const int wn   = w >> 2;         // 2 n-warps
    const int g    = lane >> 2;
    const int tg   = lane & 3;

    __shared__ __nv_bfloat16 sAhi[128][40];
    __shared__ __nv_bfloat16 sAlo[128][40];
    __shared__ __nv_bfloat16 sBhi[128][40];
    __shared__ __nv_bfloat16 sBlo[128][40];

    float d[2][8][4];
    #pragma unroll
    for (int i = 0; i < 2; i++)
        #pragma unroll
        for (int j = 0; j < 8; j++)
            #pragma unroll
            for (int q = 0; q < 4; q++) d[i][j][q] = 0.f;

    const int lrow = tid >> 1;           // 0..127
    const int lcol = (tid & 1) * 16;     // 0 or 16

    for (int k0 = 0; k0 < K; k0 += 32) {
        // ---- stage A (fp32 -> split bf16) ----
        {
            int gr = bm + lrow;
            float4 v[4];
            if (gr < M) {
                const float4* p = (const float4*)(A + (long)gr * K + k0 + lcol);
                v[0] = p[0]; v[1] = p[1]; v[2] = p[2]; v[3] = p[3];
            } else {
                v[0] = v[1] = v[2] = v[3] = make_float4(0.f, 0.f, 0.f, 0.f);
            }
            #pragma unroll
            for (int i = 0; i < 4; i++) {
                float xs[4] = {v[i].x, v[i].y, v[i].z, v[i].w};
                #pragma unroll
                for (int j = 0; j < 4; j++) {
                    __nv_bfloat16 h = __float2bfloat16(xs[j]);
                    sAhi[lrow][lcol + i * 4 + j] = h;
                    sAlo[lrow][lcol + i * 4 + j] =
                        __float2bfloat16(xs[j] - __bfloat162float(h));
                }
            }
        }
        // ---- stage B (already split, [n][K] layout; contiguous) ----
        {
            const uint4* ph = (const uint4*)(Bhi + (long)lrow * K + k0 + lcol);
            const uint4* pl = (const uint4*)(Blo + (long)lrow * K + k0 + lcol);
            uint4 h0 = ph[0], h1 = ph[1];
            uint4 l0 = pl[0], l1 = pl[1];
            *(uint4*)&sBhi[lrow][lcol]     = h0;
            *(uint4*)&sBhi[lrow][lcol + 8] = h1;
            *(uint4*)&sBlo[lrow][lcol]     = l0;
            *(uint4*)&sBlo[lrow][lcol + 8] = l1;
        }
        __syncthreads();

        #pragma unroll
        for (int ks = 0; ks < 32; ks += 16) {
            uint32_t ahi[2][4], alo[2][4];
            const int c = ks + 2 * tg;
            #pragma unroll
            for (int fm = 0; fm < 2; fm++) {
                int r = wm * 32 + fm * 16 + g;
                ahi[fm][0] = *(const uint32_t*)&sAhi[r][c];
                ahi[fm][1] = *(const uint32_t*)&sAhi[r + 8][c];
                ahi[fm][2] = *(const uint32_t*)&sAhi[r][c + 8];
                ahi[fm][3] = *(const uint32_t*)&sAhi[r + 8][c + 8];
                alo[fm][0] = *(const uint32_t*)&sAlo[r][c];
                alo[fm][1] = *(const uint32_t*)&sAlo[r + 8][c];
                alo[fm][2] = *(const uint32_t*)&sAlo[r][c + 8];
                alo[fm][3] = *(const uint32_t*)&sAlo[r + 8][c + 8];
            }
            #pragma unroll
            for (int fn = 0; fn < 8; fn++) {
                int nb = wn * 64 + fn * 8 + g;
                uint32_t bh0 = *(const uint32_t*)&sBhi[nb][c];
                uint32_t bh1 = *(const uint32_t*)&sBhi[nb][c + 8];
                uint32_t bl0 = *(const uint32_t*)&sBlo[nb][c];
                uint32_t bl1 = *(const uint32_t*)&sBlo[nb][c + 8];
                #pragma unroll
                for (int fm = 0; fm < 2; fm++) {
                    MMA_BF16(d[fm][fn], ahi[fm], bh0, bh1);
                    MMA_BF16(d[fm][fn], ahi[fm], bl0, bl1);
                    MMA_BF16(d[fm][fn], alo[fm], bh0, bh1);
                }
            }
        }
        __syncthreads();
    }

    // ---- epilogue ----
    #pragma unroll
    for (int fn = 0; fn < 8; fn++) {
        int ncol = wn * 64 + fn * 8 + 2 * tg;
        float2 bb = *(const float2*)&bias[ncol];
        int col = coff + ncol;
        #pragma unroll
        for (int fm = 0; fm < 2; fm++) {
            int r0 = bm + wm * 32 + fm * 16 + g;
            float v0 = d[fm][fn][0] + bb.x;
            float v1 = d[fm][fn][1] + bb.y;
            float v2 = d[fm][fn][2] + bb.x;
            float v3 = d[fm][fn][3] + bb.y;
            if (ACT == 1) {
                v0 = fmaxf(v0, 0.f); v1 = fmaxf(v1, 0.f);
                v2 = fmaxf(v2, 0.f); v3 = fmaxf(v3, 0.f);
            }
            if (ACT == 2) {
                v0 = tanhf(v0); v1 = tanhf(v1);
                v2 = tanhf(v2); v3 = tanhf(v3);
            }
            if (r0 < M)     *(float2*)&C[(long)r0 * ldc + col]       = make_float2(v0, v1);
            if (r0 + 8 < M) *(float2*)&C[(long)(r0 + 8) * ldc + col] = make_float2(v2, v3);
        }
    }
}

// ---------------- gather tss/rs embeds into feature cols [128,256) ----------------
__global__ void gather_embed(const float* __restrict__ tss, const float* __restrict__ rs,
                             const int* __restrict__ nid, float* __restrict__ feat, int n)
{
    int gw   = (blockIdx.x * blockDim.x + threadIdx.x) >> 5;
    int lane = threadIdx.x & 31;
    if (gw >= n) return;
    int id = nid[gw];
    float4* out = (float4*)(feat + (long)gw * FEAT);
    if (lane < 16) {
        out[32 + lane] = ((const float4*)(tss + (long)id * 64))[lane];
    } else {
        out[48 + (lane - 16)] = ((const float4*)(rs + (long)id * 64))[lane - 16];
    }
}

// ---------------- CSR build ----------------
__global__ void zero_cnt(int n)
{
    int i = blockIdx.x * blockDim.x + threadIdx.x;
    if (i < n) g_cnt[i] = 0;
}

__global__ void hist_kernel(const int* __restrict__ dst, int total, int E, int ndst)
{
    int i = blockIdx.x * blockDim.x + threadIdx.x;
    if (i >= total) return;
    int r = i / E;
    atomicAdd(&g_cnt[r * ndst + dst[i]], 1);
}

__global__ void scan_kernel(int n)   // exclusive scan of g_cnt -> g_rowp, then zero g_cnt
{
    __shared__ int ssum[1024];
    int tid   = threadIdx.x;
    int chunk = (n + 1023) >> 10;
    int base  = tid * chunk;
    int end   = min(base + chunk, n);

    int s = 0;
    for (int i = base; i < end; i++) s += g_cnt[i];
    ssum[tid] = s;
    __syncthreads();

    for (int off = 1; off < 1024; off <<= 1) {
        int v = (tid >= off) ? ssum[tid - off] : 0;
        __syncthreads();
        ssum[tid] += v;
        __syncthreads();
    }

    int p = ssum[tid] - s;   // exclusive prefix
    for (int i = base; i < end; i++) { g_rowp[i] = p; p += g_cnt[i]; }
    if (tid == 1023) g_rowp[n] = ssum[1023];
    __syncthreads();
    for (int i = tid; i < n; i += 1024) g_cnt[i] = 0;
}

__global__ void scatter_kernel(const int* __restrict__ src, const int* __restrict__ dst,
                               int total, int E, int ndst)
{
    int i = blockIdx.x * blockDim.x + threadIdx.x;
    if (i >= total) return;
    int r   = i / E;
    int idx = r * ndst + dst[i];
    int pos = g_rowp[idx] + atomicAdd(&g_cnt[idx], 1);
    g_csr[pos] = src[i];
}

// ---------------- warp-per-dst aggregation: writes [mx | mean | sum] row of 768 ----------------
__global__ void aggregate_kernel(const float* __restrict__ feat, float* __restrict__ agg, int total)
{
    int gw   = (blockIdx.x * blockDim.x + threadIdx.x) >> 5;
    int lane = threadIdx.x & 31;
    if (gw >= total) return;

    int s = g_rowp[gw], e = g_rowp[gw + 1];
    float4 sa = make_float4(0.f, 0.f, 0.f, 0.f), sb = sa;
    float4 ma = make_float4(-INFINITY, -INFINITY, -INFINITY, -INFINITY), mb = ma;

    for (int i = s; i < e; i++) {
        int srcn = g_csr[i];
        const float4* p = (const float4*)(feat + (long)srcn * FEAT);
        float4 va = p[lane];
        float4 vb = p[lane + 32];
        sa = f4add(sa, va);  sb = f4add(sb, vb);
        ma = f4max(ma, va);  mb = f4max(mb, vb);
    }

    float deg = (float)(e - s);
    if (e == s) { ma = make_float4(0.f,0.f,0.f,0.f); mb = ma; }
    float inv = 1.f / fmaxf(deg, 1.f);

    float4* o = (float4*)(agg + (long)gw * 768);
    o[lane]       = ma;                 o[32 + lane]  = mb;
    o[64 + lane]  = f4scale(sa, inv);   o[96 + lane]  = f4scale(sb, inv);
    o[128 + lane] = sa;                 o[160 + lane] = sb;
}

// ---------------- attention: score reduce + combine ----------------
__global__ void zero_wsum()
{
    if (threadIdx.x < RR) g_wsum[threadIdx.x] = 0.f;
}

__global__ void attn_reduce(const float* __restrict__ T, const float* __restrict__ w2, int N)
{
    int r = blockIdx.y;
    long total = (long)N * HID;
    const float* Tr = T + (long)r * total;

    float s = 0.f;
    for (long i = (long)blockIdx.x * blockDim.x + threadIdx.x; i < total;
         i += (long)gridDim.x * blockDim.x)
        s += Tr[i] * w2[(int)(i & 127)];

    for (int off = 16; off > 0; off >>= 1) s += __shfl_down_sync(0xffffffffu, s, off);
    __shared__ float sm[8];
    int wid = threadIdx.x >> 5, lane = threadIdx.x & 31;
    if (lane == 0) sm[wid] = s;
    __syncthreads();
    if (wid == 0) {
        s = (lane < (blockDim.x >> 5)) ? sm[lane] : 0.f;
        for (int off = 4; off > 0; off >>= 1) s += __shfl_down_sync(0xffffffffu, s, off);
        if (lane == 0) atomicAdd(&g_wsum[r], s);
    }
}

__global__ void combine_kernel(const float* __restrict__ z, int N,
                               float* __restrict__ out, int ldo,
                               const float* __restrict__ tss, const float* __restrict__ rs,
                               const int* __restrict__ nid, int do_relu, int do_gather)
{
    int gw   = (blockIdx.x * blockDim.x + threadIdx.x) >> 5;
    int lane = threadIdx.x & 31;
    if (gw >= N) return;

    float w0 = g_wsum[0] / (float)N;
    float w1 = g_wsum[1] / (float)N;
    float w2 = g_wsum[2] / (float)N;
    float m  = fmaxf(w0, fmaxf(w1, w2));
    float e0 = expf(w0 - m), e1 = expf(w1 - m), e2 = expf(w2 - m);
    float inv = 1.f / (e0 + e1 + e2);
    float b0 = e0 * inv, b1 = e1 * inv, b2 = e2 * inv;

    long stride = (long)N * HID;
    const float4* z0 = (const float4*)(z + (long)gw * HID);
    const float4* z1 = (const float4*)(z + stride + (long)gw * HID);
    const float4* z2 = (const float4*)(z + 2 * stride + (long)gw * HID);
    float4 v0 = z0[lane], v1 = z1[lane], v2 = z2[lane];
    float4 h;
    h.x = b0 * v0.x + b1 * v1.x + b2 * v2.x;
    h.y = b0 * v0.y + b1 * v1.y + b2 * v2.y;
    h.z = b0 * v0.z + b1 * v1.z + b2 * v2.z;
    h.w = b0 * v0.w + b1 * v1.w + b2 * v2.w;
    if (do_relu) { h.x = fmaxf(h.x, 0.f); h.y = fmaxf(h.y, 0.f); h.z = fmaxf(h.z, 0.f); h.w = fmaxf(h.w, 0.f); }

    float4* orow = (float4*)(out + (long)gw * ldo);
    orow[lane] = h;

    if (do_gather) {
        int id = nid[gw];
        if (lane < 16) orow[32 + lane] = ((const float4*)(tss + (long)id * 64))[lane];
        else           orow[48 + (lane - 16)] = ((const float4*)(rs + (long)id * 64))[lane - 16];
    }
}

// ---------------- final prediction ----------------
__global__ void pred_kernel(const float* __restrict__ h, const float* __restrict__ pw,
                            const float* __restrict__ pb, float* __restrict__ out, int N)
{
    int gw   = (blockIdx.x * blockDim.x + threadIdx.x) >> 5;
    int lane = threadIdx.x & 31;
    if (gw >= N) return;
    float4 v = ((const float4*)(h + (long)gw * HID))[lane];
    float4 w = ((const float4*)pw)[lane];
    float s  = v.x * w.x + v.y * w.y + v.z * w.z + v.w * w.w;
    for (int off = 16; off > 0; off >>= 1) s += __shfl_down_sync(0xffffffffu, s, off);
    if (lane == 0) out[gw] = 1.f / (1.f + expf(-(s + pb[0])));
}

// ---------------- host ----------------
extern "C" void kernel_launch(void* const* d_in, const int* in_sizes, int n_in,
                              void* d_out, int out_size)
{
    const float* x_user   = (const float*)d_in[0];
    const float* tss      = (const float*)d_in[1];
    const float* rs       = (const float*)d_in[2];
    const int*   src_nid0 = (const int*)  d_in[3];
    const int*   src_nid1 = (const int*)  d_in[4];
    const int*   e0_src   = (const int*)  d_in[5];
    const int*   e0_dst   = (const int*)  d_in[6];
    const int*   e1_src   = (const int*)  d_in[7];
    const int*   e1_dst   = (const int*)  d_in[8];
    const float* embed_w  = (const float*)d_in[9];
    const float* embed_b  = (const float*)d_in[10];
    const float* l1_fc1_w = (const float*)d_in[11];
    const float* l1_fc1_b = (const float*)d_in[12];
    const float* l1_fc2_w = (const float*)d_in[13];
    const float* l1_fc2_b = (const float*)d_in[14];
    const float* l1_fc3_w = (const float*)d_in[15];
    const float* l1_fc3_b = (const float*)d_in[16];
    const float* l2_fc1_w = (const float*)d_in[17];
    const float* l2_fc1_b = (const float*)d_in[18];
    const float* l2_fc2_w = (const float*)d_in[19];
    const float* l2_fc2_b = (const float*)d_in[20];
    const float* l2_fc3_w = (const float*)d_in[21];
    const float* l2_fc3_b = (const float*)d_in[22];
    const float* attn_w1  = (const float*)d_in[23];
    const float* attn_b1  = (const float*)d_in[24];
    const float* attn_w2  = (const float*)d_in[25];
    const float* pred_w   = (const float*)d_in[26];
    const float* pred_b   = (const float*)d_in[27];
    float* out = (float*)d_out;

    float *feat0, *agg, *scratch, *z, *feat1, *h2;
    __nv_bfloat16 *whi, *wlo;
    cudaGetSymbolAddress((void**)&feat0,   g_feat0);
    cudaGetSymbolAddress((void**)&agg,     g_agg);
    cudaGetSymbolAddress((void**)&scratch, g_scratch);
    cudaGetSymbolAddress((void**)&z,       g_z);
    cudaGetSymbolAddress((void**)&feat1,   g_feat1);
    cudaGetSymbolAddress((void**)&h2,      g_h2);
    cudaGetSymbolAddress((void**)&whi,     g_whi);
    cudaGetSymbolAddress((void**)&wlo,     g_wlo);

    dim3 tb(32, 8);
    // ---- split + transpose all weights into bf16 hi/lo ----
    split_w<<<dim3(128/32, 4, 1),  tb>>>(embed_w,  whi + OFF_EMBED, wlo + OFF_EMBED, 128);
    split_w<<<dim3(256/32, 4, RR), tb>>>(l1_fc1_w, whi + OFF_L1FC1, wlo + OFF_L1FC1, 256);
    split_w<<<dim3(768/32, 4, RR), tb>>>(l1_fc2_w, whi + OFF_L1FC2, wlo + OFF_L1FC2, 768);
    split_w<<<dim3(256/32, 4, RR), tb>>>(l1_fc3_w, whi + OFF_L1FC3, wlo + OFF_L1FC3, 256);
    split_w<<<dim3(256/32, 4, RR), tb>>>(l2_fc1_w, whi + OFF_L2FC1, wlo + OFF_L2FC1, 256);
    split_w<<<dim3(768/32, 4, RR), tb>>>(l2_fc2_w, whi + OFF_L2FC2, wlo + OFF_L2FC2, 768);
    split_w<<<dim3(256/32, 4, RR), tb>>>(l2_fc3_w, whi + OFF_L2FC3, wlo + OFF_L2FC3, 256);
    split_w<<<dim3(128/32, 4, 1),  tb>>>(attn_w1,  whi + OFF_ATTN,  wlo + OFF_ATTN,  128);

    // ---- embed + feat0 ----
    tc_gemm<0><<<dim3(CDIV(NN0,128),1,1),256>>>(x_user, whi+OFF_EMBED, wlo+OFF_EMBED, embed_b,
        feat0, NN0, 128, FEAT, 0, 0,0,0,0);
    gather_embed<<<CDIV(NN0*32,256),256>>>(tss, rs, src_nid0, feat0, NN0);

    // ---- layer 1 CSR + aggregate ----
    zero_cnt<<<CDIV(RR*NN1,256),256>>>(RR*NN1);
    hist_kernel<<<CDIV(RR*EE0,256),256>>>(e0_dst, RR*EE0, EE0, NN1);
    scan_kernel<<<1,1024>>>(RR*NN1);
    scatter_kernel<<<CDIV(RR*EE0,256),256>>>(e0_src, e0_dst, RR*EE0, EE0, NN1);
    aggregate_kernel<<<CDIV(RR*NN1*32,256),256>>>(feat0, agg, RR*NN1);

    // ---- layer 1 GEMMs (batched over relations) ----
    tc_gemm<1><<<dim3(CDIV(NN1,128),1,RR),256>>>(agg,   whi+OFF_L1FC2, wlo+OFF_L1FC2, l1_fc2_b,
        scratch, NN1, 768, FEAT, 0,   (long)NN1*768, 768*128, 128, (long)NN1*FEAT);
    tc_gemm<1><<<dim3(CDIV(NN1,128),1,RR),256>>>(feat0, whi+OFF_L1FC1, wlo+OFF_L1FC1, l1_fc1_b,
        scratch, NN1, 256, FEAT, 128, 0,             256*128, 128, (long)NN1*FEAT);
    tc_gemm<0><<<dim3(CDIV(NN1,128),1,RR),256>>>(scratch, whi+OFF_L1FC3, wlo+OFF_L1FC3, l1_fc3_b,
        z, NN1, 256, HID, 0,    (long)NN1*FEAT, 256*128, 128, (long)NN1*HID);

    // ---- attention 1 -> feat1 ----
    tc_gemm<2><<<dim3(CDIV(RR*NN1,128),1,1),256>>>(z, whi+OFF_ATTN, wlo+OFF_ATTN, attn_b1,
        scratch, RR*NN1, 128, 128, 0, 0,0,0,0);
    zero_wsum<<<1,32>>>();
    attn_reduce<<<dim3(240,RR),256>>>(scratch, attn_w2, NN1);
    combine_kernel<<<CDIV(NN1*32,256),256>>>(z, NN1, feat1, FEAT, tss, rs, src_nid1, 1, 1);

    // ---- layer 2 CSR + aggregate ----
    zero_cnt<<<CDIV(RR*NN2,256),256>>>(RR*NN2);
    hist_kernel<<<CDIV(RR*EE1,256),256>>>(e1_dst, RR*EE1, EE1, NN2);
    scan_kernel<<<1,1024>>>(RR*NN2);
    scatter_kernel<<<CDIV(RR*EE1,256),256>>>(e1_src, e1_dst, RR*EE1, EE1, NN2);
    aggregate_kernel<<<CDIV(RR*NN2*32,256),256>>>(feat1, agg, RR*NN2);

    // ---- layer 2 GEMMs ----
    tc_gemm<1><<<dim3(CDIV(NN2,128),1,RR),256>>>(agg,   whi+OFF_L2FC2, wlo+OFF_L2FC2, l2_fc2_b,
        scratch, NN2, 768, FEAT, 0,   (long)NN2*768, 768*128, 128, (long)NN2*FEAT);
    tc_gemm<1><<<dim3(CDIV(NN2,128),1,RR),256>>>(feat1, whi+OFF_L2FC1, wlo+OFF_L2FC1, l2_fc1_b,
        scratch, NN2, 256, FEAT, 128, 0,             256*128, 128, (long)NN2*FEAT);
    tc_gemm<0><<<dim3(CDIV(NN2,128),1,RR),256>>>(scratch, whi+OFF_L2FC3, wlo+OFF_L2FC3, l2_fc3_b,
        z, NN2, 256, HID, 0,    (long)NN2*FEAT, 256*128, 128, (long)NN2*HID);

    // ---- attention 2 -> h2 -> prediction ----
    tc_gemm<2><<<dim3(CDIV(RR*NN2,128),1,1),256>>>(z, whi+OFF_ATTN, wlo+OFF_ATTN, attn_b1,
        scratch, RR*NN2, 128, 128, 0, 0,0,0,0);
    zero_wsum<<<1,32>>>();
    attn_reduce<<<dim3(48,RR),256>>>(scratch, attn_w2, NN2);
    combine_kernel<<<CDIV(NN2*32,256),256>>>(z, NN2, h2, HID, (const float*)0, (const float*)0,
                                             (const int*)0, 0, 0);
    pred_kernel<<<CDIV(NN2*32,256),256>>>(h2, pred_w, pred_b, out, NN2);
}

// round 4
// speedup vs baseline: 1.9574x; 1.1943x over previous
#include <cuda_runtime.h>
#include <cuda_bf16.h>
#include <math.h>
#include <stdint.h>

// ---------------- problem constants ----------------
#define NN0 100000
#define NN1 20000
#define NN2 4000
#define RR 3
#define EE0 160000
#define EE1 64000
#define HID 128
#define FEAT 256      // F_IN = HID + TSS + RS
#define CDIV(a,b) (((a)+(b)-1)/(b))

// ---------------- device scratch (static; no runtime alloc) ----------------
__device__ float g_feat0[(size_t)NN0 * FEAT];          // [N0,256]
__device__ float g_agg[(size_t)RR * NN1 * 768];        // [R,n_dst,768] (mx|mean|sum)
__device__ float g_scratch[(size_t)RR * NN1 * FEAT];   // inp [R,n,256] / tanh buf [R*n,128]
__device__ float g_z[(size_t)RR * NN1 * HID];          // z per relation
__device__ float g_feat1[(size_t)NN1 * FEAT];          // [N1,256]
__device__ float g_h2[(size_t)NN2 * HID];              // [N2,128]
__device__ float g_wsum[RR];                           // attention score sums
__device__ int   g_cnt[RR * NN1];                      // histogram / cursor
__device__ int   g_rowp[RR * NN1 + 1];                 // CSR row pointers
__device__ int   g_csr[RR * EE0];                      // CSR src ids

// split-bf16 weights, transposed to [n=128][K] layout
#define W_TOTAL 1015808
__device__ __align__(16) __nv_bfloat16 g_whi[W_TOTAL];
__device__ __align__(16) __nv_bfloat16 g_wlo[W_TOTAL];

// offsets (elements) into g_whi/g_wlo
#define OFF_EMBED  0
#define OFF_L1FC1  16384
#define OFF_L1FC2  114688
#define OFF_L1FC3  409600
#define OFF_L2FC1  507904
#define OFF_L2FC2  606208
#define OFF_L2FC3  901120
#define OFF_ATTN   999424

// ---------------- small helpers ----------------
__device__ __forceinline__ float4 f4add(float4 a, float4 b){
    return make_float4(a.x+b.x, a.y+b.y, a.z+b.z, a.w+b.w);
}
__device__ __forceinline__ float4 f4max(float4 a, float4 b){
    return make_float4(fmaxf(a.x,b.x), fmaxf(a.y,b.y), fmaxf(a.z,b.z), fmaxf(a.w,b.w));
}
__device__ __forceinline__ float4 f4scale(float4 a, float s){
    return make_float4(a.x*s, a.y*s, a.z*s, a.w*s);
}

#define MMA_BF16(D, A, B0, B1) \
  asm volatile("mma.sync.aligned.m16n8k16.row.col.f32.bf16.bf16.f32 " \
    "{%0,%1,%2,%3}, {%4,%5,%6,%7}, {%8,%9}, {%0,%1,%2,%3};\n" \
    : "+f"((D)[0]), "+f"((D)[1]), "+f"((D)[2]), "+f"((D)[3]) \
    : "r"((A)[0]), "r"((A)[1]), "r"((A)[2]), "r"((A)[3]), "r"(B0), "r"(B1))

#define LDSM_X4(R0,R1,R2,R3, ADDR) \
  asm volatile("ldmatrix.sync.aligned.m8n8.x4.shared.b16 {%0,%1,%2,%3},[%4];" \
    : "=r"(R0), "=r"(R1), "=r"(R2), "=r"(R3) : "r"(ADDR))

__device__ __forceinline__ uint32_t smem_u32(const void* p){
    return (uint32_t)__cvta_generic_to_shared(p);
}

// ---------------- fused weight transpose+split: all matrices in one launch ----------------
struct WJob { const float* src; long doff; int K; int pad; };
struct WJobs { WJob j[20]; };

__global__ void split_all(WJobs jobs, __nv_bfloat16* __restrict__ Whi,
                          __nv_bfloat16* __restrict__ Wlo)
{
    WJob jb = jobs.j[blockIdx.z];
    int K = jb.K;
    int k0 = blockIdx.x * 32;
    if (k0 >= K) return;
    int n0 = blockIdx.y * 32;
    const float* W = jb.src;
    __nv_bfloat16* whi = Whi + jb.doff;
    __nv_bfloat16* wlo = Wlo + jb.doff;

    __shared__ float sm[32][33];
    int tx = threadIdx.x, ty = threadIdx.y;
    #pragma unroll
    for (int i = 0; i < 4; i++)
        sm[ty + i * 8][tx] = W[(long)(k0 + ty + i * 8) * 128 + n0 + tx];
    __syncthreads();
    #pragma unroll
    for (int i = 0; i < 4; i++) {
        float x = sm[tx][ty + i * 8];
        __nv_bfloat16 h = __float2bfloat16(x);
        float r = x - __bfloat162float(h);
        int n = n0 + ty + i * 8;
        whi[(long)n * K + k0 + tx] = h;
        wlo[(long)n * K + k0 + tx] = __float2bfloat16(r);
    }
}

// ---------------- tensor-core GEMM: C[M,128] = act(A[M,K] @ W[K,128] + bias) ----------------
// W pre-split+transposed as Bhi/Blo [128][K]. Batched over blockIdx.z.
// ACT: 0=none 1=relu 2=tanh
template<int ACT>
__global__ __launch_bounds__(256, 2)
void tc_gemm(const float* __restrict__ A, const __nv_bfloat16* __restrict__ Bhi,
             const __nv_bfloat16* __restrict__ Blo, const float* __restrict__ bias,
             float* __restrict__ C, int M, int K, int ldc, int coff,
             long sA, long sW, long sBias, long sC)
{
    A    += (long)blockIdx.z * sA;
    Bhi  += (long)blockIdx.z * sW;
    Blo  += (long)blockIdx.z * sW;
    bias += (long)blockIdx.z * sBias;
    C    += (long)blockIdx.z * sC;

    const int bm   = blockIdx.x * 128;
    const int tid  = threadIdx.x;
    const int lane = tid & 31;
    const int w    = tid >> 5;
    const int wm   = w & 3;          // 4 m-warps
    const int wn   = w >> 2;         // 2 n-warps
    const int g    = lane >> 2;
    const int tg   = lane & 3;

    __shared__ __nv_bfloat16 sAhi[128][40];
    __shared__ __nv_bfloat16 sAlo[128][40];
    __shared__ __nv_bfloat16 sBhi[128][40];
    __shared__ __nv_bfloat16 sBlo[128][40];

    float d[2][8][4];
    #pragma unroll
    for (int i = 0; i < 2; i++)
        #pragma unroll
        for (int j = 0; j < 8; j++)
            #pragma unroll
            for (int q = 0; q < 4; q++) d[i][j][q] = 0.f;

    const int lrow = tid >> 1;           // 0..127
    const int lcol = (tid & 1) * 16;     // 0 or 16

    // ldmatrix row/col selector for this lane
    const int lm_r = lane & 15;
    const int lm_c = (lane >> 4) << 3;   // 0 or 8

    for (int k0 = 0; k0 < K; k0 += 32) {
        // ---- stage A (fp32 -> split bf16, packed 128-bit stores) ----
        {
            int gr = bm + lrow;
            float4 v[4];
            if (gr < M) {
                const float4* p = (const float4*)(A + (long)gr * K + k0 + lcol);
                v[0] = p[0]; v[1] = p[1]; v[2] = p[2]; v[3] = p[3];
            } else {
                v[0] = v[1] = v[2] = v[3] = make_float4(0.f, 0.f, 0.f, 0.f);
            }
            uint32_t hi[8], lo[8];
            #pragma unroll
            for (int i = 0; i < 4; i++) {
                float x0 = v[i].x, x1 = v[i].y, x2 = v[i].z, x3 = v[i].w;
                __nv_bfloat162 h01 = __floats2bfloat162_rn(x0, x1);
                __nv_bfloat162 h23 = __floats2bfloat162_rn(x2, x3);
                __nv_bfloat162 l01 = __floats2bfloat162_rn(x0 - __low2float(h01),
                                                           x1 - __high2float(h01));
                __nv_bfloat162 l23 = __floats2bfloat162_rn(x2 - __low2float(h23),
                                                           x3 - __high2float(h23));
                hi[2*i]   = *(uint32_t*)&h01;
                hi[2*i+1] = *(uint32_t*)&h23;
                lo[2*i]   = *(uint32_t*)&l01;
                lo[2*i+1] = *(uint32_t*)&l23;
            }
            *(uint4*)&sAhi[lrow][lcol]     = make_uint4(hi[0], hi[1], hi[2], hi[3]);
            *(uint4*)&sAhi[lrow][lcol + 8] = make_uint4(hi[4], hi[5], hi[6], hi[7]);
            *(uint4*)&sAlo[lrow][lcol]     = make_uint4(lo[0], lo[1], lo[2], lo[3]);
            *(uint4*)&sAlo[lrow][lcol + 8] = make_uint4(lo[4], lo[5], lo[6], lo[7]);
        }
        // ---- stage B (already split, [n][K] layout; contiguous 128-bit copies) ----
        {
            const uint4* ph = (const uint4*)(Bhi + (long)lrow * K + k0 + lcol);
            const uint4* pl = (const uint4*)(Blo + (long)lrow * K + k0 + lcol);
            uint4 h0 = ph[0], h1 = ph[1];
            uint4 l0 = pl[0], l1 = pl[1];
            *(uint4*)&sBhi[lrow][lcol]     = h0;
            *(uint4*)&sBhi[lrow][lcol + 8] = h1;
            *(uint4*)&sBlo[lrow][lcol]     = l0;
            *(uint4*)&sBlo[lrow][lcol + 8] = l1;
        }
        __syncthreads();

        #pragma unroll
        for (int ks = 0; ks < 32; ks += 16) {
            const int c = ks + lm_c;
            // A fragments via ldmatrix.x4 (hi + lo, 2 m-tiles each)
            uint32_t ah[2][4], al[2][4];
            #pragma unroll
            for (int fm = 0; fm < 2; fm++) {
                int r = wm * 32 + fm * 16 + lm_r;
                LDSM_X4(ah[fm][0], ah[fm][1], ah[fm][2], ah[fm][3],
                        smem_u32(&sAhi[r][c]));
                LDSM_X4(al[fm][0], al[fm][1], al[fm][2], al[fm][3],
                        smem_u32(&sAlo[r][c]));
            }
            // B fragments: one ldmatrix.x4 covers 2 fn tiles
            #pragma unroll
            for (int t = 0; t < 4; t++) {
                int nb = wn * 64 + t * 16 + lm_r;
                uint32_t bh0, bh1, bh2, bh3, bl0, bl1, bl2, bl3;
                LDSM_X4(bh0, bh1, bh2, bh3, smem_u32(&sBhi[nb][c]));
                LDSM_X4(bl0, bl1, bl2, bl3, smem_u32(&sBlo[nb][c]));
                #pragma unroll
                for (int fm = 0; fm < 2; fm++) {
                    MMA_BF16(d[fm][2*t],   ah[fm], bh0, bh2);
                    MMA_BF16(d[fm][2*t],   ah[fm], bl0, bl2);
                    MMA_BF16(d[fm][2*t],   al[fm], bh0, bh2);
                    MMA_BF16(d[fm][2*t+1], ah[fm], bh1, bh3);
                    MMA_BF16(d[fm][2*t+1], ah[fm], bl1, bl3);
                    MMA_BF16(d[fm][2*t+1], al[fm], bh1, bh3);
                }
            }
        }
        __syncthreads();
    }

    // ---- epilogue ----
    #pragma unroll
    for (int fn = 0; fn < 8; fn++) {
        int ncol = wn * 64 + fn * 8 + 2 * tg;
        float2 bb = *(const float2*)&bias[ncol];
        int col = coff + ncol;
        #pragma unroll
        for (int fm = 0; fm < 2; fm++) {
            int r0 = bm + wm * 32 + fm * 16 + g;
            float v0 = d[fm][fn][0] + bb.x;
            float v1 = d[fm][fn][1] + bb.y;
            float v2 = d[fm][fn][2] + bb.x;
            float v3 = d[fm][fn][3] + bb.y;
            if (ACT == 1) {
                v0 = fmaxf(v0, 0.f); v1 = fmaxf(v1, 0.f);
                v2 = fmaxf(v2, 0.f); v3 = fmaxf(v3, 0.f);
            }
            if (ACT == 2) {
                v0 = tanhf(v0); v1 = tanhf(v1);
                v2 = tanhf(v2); v3 = tanhf(v3);
            }
            if (r0 < M)     *(float2*)&C[(long)r0 * ldc + col]       = make_float2(v0, v1);
            if (r0 + 8 < M) *(float2*)&C[(long)(r0 + 8) * ldc + col] = make_float2(v2, v3);
        }
    }
}

// ---------------- gather tss/rs embeds into feature cols [128,256) ----------------
__global__ void gather_embed(const float* __restrict__ tss, const float* __restrict__ rs,
                             const int* __restrict__ nid, float* __restrict__ feat, int n)
{
    int gw   = (blockIdx.x * blockDim.x + threadIdx.x) >> 5;
    int lane = threadIdx.x & 31;
    if (gw >= n) return;
    int id = nid[gw];
    float4* out = (float4*)(feat + (long)gw * FEAT);
    if (lane < 16) {
        out[32 + lane] = ((const float4*)(tss + (long)id * 64))[lane];
    } else {
        out[48 + (lane - 16)] = ((const float4*)(rs + (long)id * 64))[lane - 16];
    }
}

// ---------------- CSR build ----------------
__global__ void zero_cnt(int n)
{
    int i = blockIdx.x * blockDim.x + threadIdx.x;
    if (i < n) g_cnt[i] = 0;
}

__global__ void hist_kernel(const int* __restrict__ dst, int total, int E, int ndst)
{
    int i = blockIdx.x * blockDim.x + threadIdx.x;
    if (i >= total) return;
    int r = i / E;
    atomicAdd(&g_cnt[r * ndst + dst[i]], 1);
}

__global__ void scan_kernel(int n)   // exclusive scan of g_cnt -> g_rowp, then zero g_cnt
{
    __shared__ int ssum[1024];
    int tid   = threadIdx.x;
    int chunk = (n + 1023) >> 10;
    int base  = tid * chunk;
    int end   = min(base + chunk, n);

    int s = 0;
    for (int i = base; i < end; i++) s += g_cnt[i];
    ssum[tid] = s;
    __syncthreads();

    for (int off = 1; off < 1024; off <<= 1) {
        int v = (tid >= off) ? ssum[tid - off] : 0;
        __syncthreads();
        ssum[tid] += v;
        __syncthreads();
    }

    int p = ssum[tid] - s;   // exclusive prefix
    for (int i = base; i < end; i++) { g_rowp[i] = p; p += g_cnt[i]; }
    if (tid == 1023) g_rowp[n] = ssum[1023];
    __syncthreads();
    for (int i = tid; i < n; i += 1024) g_cnt[i] = 0;
}

__global__ void scatter_kernel(const int* __restrict__ src, const int* __restrict__ dst,
                               int total, int E, int ndst)
{
    int i = blockIdx.x * blockDim.x + threadIdx.x;
    if (i >= total) return;
    int r   = i / E;
    int idx = r * ndst + dst[i];
    int pos = g_rowp[idx] + atomicAdd(&g_cnt[idx], 1);
    g_csr[pos] = src[i];
}

// ---------------- warp-per-dst aggregation: writes [mx | mean | sum] row of 768 ----------------
__global__ void aggregate_kernel(const float* __restrict__ feat, float* __restrict__ agg, int total)
{
    int gw   = (blockIdx.x * blockDim.x + threadIdx.x) >> 5;
    int lane = threadIdx.x & 31;
    if (gw >= total) return;

    int s = g_rowp[gw], e = g_rowp[gw + 1];
    float4 sa = make_float4(0.f, 0.f, 0.f, 0.f), sb = sa;
    float4 ma = make_float4(-INFINITY, -INFINITY, -INFINITY, -INFINITY), mb = ma;

    int i = s;
    for (; i + 1 < e; i += 2) {
        int s0 = g_csr[i], s1 = g_csr[i + 1];
        const float4* p0 = (const float4*)(feat + (long)s0 * FEAT);
        const float4* p1 = (const float4*)(feat + (long)s1 * FEAT);
        float4 va0 = p0[lane], vb0 = p0[lane + 32];
        float4 va1 = p1[lane], vb1 = p1[lane + 32];
        sa = f4add(sa, f4add(va0, va1));  sb = f4add(sb, f4add(vb0, vb1));
        ma = f4max(ma, f4max(va0, va1));  mb = f4max(mb, f4max(vb0, vb1));
    }
    if (i < e) {
        int s0 = g_csr[i];
        const float4* p0 = (const float4*)(feat + (long)s0 * FEAT);
        float4 va0 = p0[lane], vb0 = p0[lane + 32];
        sa = f4add(sa, va0);  sb = f4add(sb, vb0);
        ma = f4max(ma, va0);  mb = f4max(mb, vb0);
    }

    float deg = (float)(e - s);
    if (e == s) { ma = make_float4(0.f,0.f,0.f,0.f); mb = ma; }
    float inv = 1.f / fmaxf(deg, 1.f);

    float4* o = (float4*)(agg + (long)gw * 768);
    o[lane]       = ma;                 o[32 + lane]  = mb;
    o[64 + lane]  = f4scale(sa, inv);   o[96 + lane]  = f4scale(sb, inv);
    o[128 + lane] = sa;                 o[160 + lane] = sb;
}

// ---------------- attention: score reduce + combine ----------------
__global__ void zero_wsum()
{
    if (threadIdx.x < RR) g_wsum[threadIdx.x] = 0.f;
}

__global__ void attn_reduce(const float* __restrict__ T, const float* __restrict__ w2, int N)
{
    int r = blockIdx.y;
    long total = (long)N * HID;
    const float* Tr = T + (long)r * total;

    float s = 0.f;
    for (long i = (long)blockIdx.x * blockDim.x + threadIdx.x; i < total;
         i += (long)gridDim.x * blockDim.x)
        s += Tr[i] * w2[(int)(i & 127)];

    for (int off = 16; off > 0; off >>= 1) s += __shfl_down_sync(0xffffffffu, s, off);
    __shared__ float sm[8];
    int wid = threadIdx.x >> 5, lane = threadIdx.x & 31;
    if (lane == 0) sm[wid] = s;
    __syncthreads();
    if (wid == 0) {
        s = (lane < (blockDim.x >> 5)) ? sm[lane] : 0.f;
        for (int off = 4; off > 0; off >>= 1) s += __shfl_down_sync(0xffffffffu, s, off);
        if (lane == 0) atomicAdd(&g_wsum[r], s);
    }
}

__global__ void combine_kernel(const float* __restrict__ z, int N,
                               float* __restrict__ out, int ldo,
                               const float* __restrict__ tss, const float* __restrict__ rs,
                               const int* __restrict__ nid, int do_relu, int do_gather)
{
    int gw   = (blockIdx.x * blockDim.x + threadIdx.x) >> 5;
    int lane = threadIdx.x & 31;
    if (gw >= N) return;

    float w0 = g_wsum[0] / (float)N;
    float w1 = g_wsum[1] / (float)N;
    float w2 = g_wsum[2] / (float)N;
    float m  = fmaxf(w0, fmaxf(w1, w2));
    float e0 = expf(w0 - m), e1 = expf(w1 - m), e2 = expf(w2 - m);
    float inv = 1.f / (e0 + e1 + e2);
    float b0 = e0 * inv, b1 = e1 * inv, b2 = e2 * inv;

    long stride = (long)N * HID;
    const float4* z0 = (const float4*)(z + (long)gw * HID);
    const float4* z1 = (const float4*)(z + stride + (long)gw * HID);
    const float4* z2 = (const float4*)(z + 2 * stride + (long)gw * HID);
    float4 v0 = z0[lane], v1 = z1[lane], v2 = z2[lane];
    float4 h;
    h.x = b0 * v0.x + b1 * v1.x + b2 * v2.x;
    h.y = b0 * v0.y + b1 * v1.y + b2 * v2.y;
    h.z = b0 * v0.z + b1 * v1.z + b2 * v2.z;
    h.w = b0 * v0.w + b1 * v1.w + b2 * v2.w;
    if (do_relu) { h.x = fmaxf(h.x, 0.f); h.y = fmaxf(h.y, 0.f); h.z = fmaxf(h.z, 0.f); h.w = fmaxf(h.w, 0.f); }

    float4* orow = (float4*)(out + (long)gw * ldo);
    orow[lane] = h;

    if (do_gather) {
        int id = nid[gw];
        if (lane < 16) orow[32 + lane] = ((const float4*)(tss + (long)id * 64))[lane];
        else           orow[48 + (lane - 16)] = ((const float4*)(rs + (long)id * 64))[lane - 16];
    }
}

// ---------------- final prediction ----------------
__global__ void pred_kernel(const float* __restrict__ h, const float* __restrict__ pw,
                            const float* __restrict__ pb, float* __restrict__ out, int N)
{
    int gw   = (blockIdx.x * blockDim.x + threadIdx.x) >> 5;
    int lane = threadIdx.x & 31;
    if (gw >= N) return;
    float4 v = ((const float4*)(h + (long)gw * HID))[lane];
    float4 w = ((const float4*)pw)[lane];
    float s  = v.x * w.x + v.y * w.y + v.z * w.z + v.w * w.w;
    for (int off = 16; off > 0; off >>= 1) s += __shfl_down_sync(0xffffffffu, s, off);
    if (lane == 0) out[gw] = 1.f / (1.f + expf(-(s + pb[0])));
}

// ---------------- host ----------------
extern "C" void kernel_launch(void* const* d_in, const int* in_sizes, int n_in,
                              void* d_out, int out_size)
{
    const float* x_user   = (const float*)d_in[0];
    const float* tss      = (const float*)d_in[1];
    const float* rs       = (const float*)d_in[2];
    const int*   src_nid0 = (const int*)  d_in[3];
    const int*   src_nid1 = (const int*)  d_in[4];
    const int*   e0_src   = (const int*)  d_in[5];
    const int*   e0_dst   = (const int*)  d_in[6];
    const int*   e1_src   = (const int*)  d_in[7];
    const int*   e1_dst   = (const int*)  d_in[8];
    const float* embed_w  = (const float*)d_in[9];
    const float* embed_b  = (const float*)d_in[10];
    const float* l1_fc1_w = (const float*)d_in[11];
    const float* l1_fc1_b = (const float*)d_in[12];
    const float* l1_fc2_w = (const float*)d_in[13];
    const float* l1_fc2_b = (const float*)d_in[14];
    const float* l1_fc3_w = (const float*)d_in[15];
    const float* l1_fc3_b = (const float*)d_in[16];
    const float* l2_fc1_w = (const float*)d_in[17];
    const float* l2_fc1_b = (const float*)d_in[18];
    const float* l2_fc2_w = (const float*)d_in[19];
    const float* l2_fc2_b = (const float*)d_in[20];
    const float* l2_fc3_w = (const float*)d_in[21];
    const float* l2_fc3_b = (const float*)d_in[22];
    const float* attn_w1  = (const float*)d_in[23];
    const float* attn_b1  = (const float*)d_in[24];
    const float* attn_w2  = (const float*)d_in[25];
    const float* pred_w   = (const float*)d_in[26];
    const float* pred_b   = (const float*)d_in[27];
    float* out = (float*)d_out;

    float *feat0, *agg, *scratch, *z, *feat1, *h2;
    __nv_bfloat16 *whi, *wlo;
    cudaGetSymbolAddress((void**)&feat0,   g_feat0);
    cudaGetSymbolAddress((void**)&agg,     g_agg);
    cudaGetSymbolAddress((void**)&scratch, g_scratch);
    cudaGetSymbolAddress((void**)&z,       g_z);
    cudaGetSymbolAddress((void**)&feat1,   g_feat1);
    cudaGetSymbolAddress((void**)&h2,      g_h2);
    cudaGetSymbolAddress((void**)&whi,     g_whi);
    cudaGetSymbolAddress((void**)&wlo,     g_wlo);

    // ---- fused weight split: one launch for all 20 matrices ----
    WJobs jobs;
    {
        int n = 0;
        jobs.j[n++] = {embed_w, OFF_EMBED, 128, 0};
        for (int r = 0; r < RR; r++)
            jobs.j[n++] = {l1_fc1_w + (long)r*256*128, OFF_L1FC1 + (long)r*256*128, 256, 0};
        for (int r = 0; r < RR; r++)
            jobs.j[n++] = {l1_fc2_w + (long)r*768*128, OFF_L1FC2 + (long)r*768*128, 768, 0};
        for (int r = 0; r < RR; r++)
            jobs.j[n++] = {l1_fc3_w + (long)r*256*128, OFF_L1FC3 + (long)r*256*128, 256, 0};
        for (int r = 0; r < RR; r++)
            jobs.j[n++] = {l2_fc1_w + (long)r*256*128, OFF_L2FC1 + (long)r*256*128, 256, 0};
        for (int r = 0; r < RR; r++)
            jobs.j[n++] = {l2_fc2_w + (long)r*768*128, OFF_L2FC2 + (long)r*768*128, 768, 0};
        for (int r = 0; r < RR; r++)
            jobs.j[n++] = {l2_fc3_w + (long)r*256*128, OFF_L2FC3 + (long)r*256*128, 256, 0};
        jobs.j[n++] = {attn_w1, OFF_ATTN, 128, 0};
    }
    split_all<<<dim3(24, 4, 20), dim3(32, 8)>>>(jobs, whi, wlo);

    // ---- embed + feat0 ----
    tc_gemm<0><<<dim3(CDIV(NN0,128),1,1),256>>>(x_user, whi+OFF_EMBED, wlo+OFF_EMBED, embed_b,
        feat0, NN0, 128, FEAT, 0, 0,0,0,0);
    gather_embed<<<CDIV(NN0*32,256),256>>>(tss, rs, src_nid0, feat0, NN0);

    // ---- layer 1 CSR + aggregate ----
    zero_cnt<<<CDIV(RR*NN1,256),256>>>(RR*NN1);
    hist_kernel<<<CDIV(RR*EE0,256),256>>>(e0_dst, RR*EE0, EE0, NN1);
    scan_kernel<<<1,1024>>>(RR*NN1);
    scatter_kernel<<<CDIV(RR*EE0,256),256>>>(e0_src, e0_dst, RR*EE0, EE0, NN1);
    aggregate_kernel<<<CDIV(RR*NN1*32,256),256>>>(feat0, agg, RR*NN1);

    // ---- layer 1 GEMMs (batched over relations) ----
    tc_gemm<1><<<dim3(CDIV(NN1,128),1,RR),256>>>(agg,   whi+OFF_L1FC2, wlo+OFF_L1FC2, l1_fc2_b,
        scratch, NN1, 768, FEAT, 0,   (long)NN1*768, 768*128, 128, (long)NN1*FEAT);
    tc_gemm<1><<<dim3(CDIV(NN1,128),1,RR),256>>>(feat0, whi+OFF_L1FC1, wlo+OFF_L1FC1, l1_fc1_b,
        scratch, NN1, 256, FEAT, 128, 0,             256*128, 128, (long)NN1*FEAT);
    tc_gemm<0><<<dim3(CDIV(NN1,128),1,RR),256>>>(scratch, whi+OFF_L1FC3, wlo+OFF_L1FC3, l1_fc3_b,
        z, NN1, 256, HID, 0,    (long)NN1*FEAT, 256*128, 128, (long)NN1*HID);

    // ---- attention 1 -> feat1 ----
    tc_gemm<2><<<dim3(CDIV(RR*NN1,128),1,1),256>>>(z, whi+OFF_ATTN, wlo+OFF_ATTN, attn_b1,
        scratch, RR*NN1, 128, 128, 0, 0,0,0,0);
    zero_wsum<<<1,32>>>();
    attn_reduce<<<dim3(240,RR),256>>>(scratch, attn_w2, NN1);
    combine_kernel<<<CDIV(NN1*32,256),256>>>(z, NN1, feat1, FEAT, tss, rs, src_nid1, 1, 1);

    // ---- layer 2 CSR + aggregate ----
    zero_cnt<<<CDIV(RR*NN2,256),256>>>(RR*NN2);
    hist_kernel<<<CDIV(RR*EE1,256),256>>>(e1_dst, RR*EE1, EE1, NN2);
    scan_kernel<<<1,1024>>>(RR*NN2);
    scatter_kernel<<<CDIV(RR*EE1,256),256>>>(e1_src, e1_dst, RR*EE1, EE1, NN2);
    aggregate_kernel<<<CDIV(RR*NN2*32,256),256>>>(feat1, agg, RR*NN2);

    // ---- layer 2 GEMMs ----
    tc_gemm<1><<<dim3(CDIV(NN2,128),1,RR),256>>>(agg,   whi+OFF_L2FC2, wlo+OFF_L2FC2, l2_fc2_b,
        scratch, NN2, 768, FEAT, 0,   (long)NN2*768, 768*128, 128, (long)NN2*FEAT);
    tc_gemm<1><<<dim3(CDIV(NN2,128),1,RR),256>>>(feat1, whi+OFF_L2FC1, wlo+OFF_L2FC1, l2_fc1_b,
        scratch, NN2, 256, FEAT, 128, 0,             256*128, 128, (long)NN2*FEAT);
    tc_gemm<0><<<dim3(CDIV(NN2,128),1,RR),256>>>(scratch, whi+OFF_L2FC3, wlo+OFF_L2FC3, l2_fc3_b,
        z, NN2, 256, HID, 0,    (long)NN2*FEAT, 256*128, 128, (long)NN2*HID);

    // ---- attention 2 -> h2 -> prediction ----
    tc_gemm<2><<<dim3(CDIV(RR*NN2,128),1,1),256>>>(z, whi+OFF_ATTN, wlo+OFF_ATTN, attn_b1,
        scratch, RR*NN2, 128, 128, 0, 0,0,0,0);
    zero_wsum<<<1,32>>>();
    attn_reduce<<<dim3(48,RR),256>>>(scratch, attn_w2, NN2);
    combine_kernel<<<CDIV(NN2*32,256),256>>>(z, NN2, h2, HID, (const float*)0, (const float*)0,
                                             (const int*)0, 0, 0);
    pred_kernel<<<CDIV(NN2*32,256),256>>>(h2, pred_w, pred_b, out, NN2);
}